// round 15
// baseline (speedup 1.0000x reference)
#include <cuda_runtime.h>
#include <math_constants.h>
#include <cstdint>

// Problem constants (fixed by setup_inputs)
#define BB 8
#define NN 2048
#define MM 2048
#define DD 256
#define KSIM 16
#define KCOOR 4
#define NCMAX 24            // 16 selected + up to 8 threshold extras
#define EPSW 1e-3f          // >> tf32 max abs error on w (~2e-4)

// ---------------- device scratch (allocation-free) ----------------
__device__ float g_f1n[(size_t)BB * NN * DD];
__device__ float g_f2n[(size_t)BB * MM * DD];
__device__ float g_w[(size_t)BB * MM * NN];   // approx (tf32) exp(w1)
__device__ float g_den1[(size_t)BB * NN];
__device__ float g_den2[(size_t)BB * MM];

// ---------------- accurate-class expf replica (frozen bit recipe) ----------------
__device__ __forceinline__ float xla_expf(float x) {
    const float exp_hi = 88.3762626647950f;
    const float exp_lo = -88.3762626647949f;
    const float LOG2EF = 1.44269504088896341f;
    const float C1     = 0.693359375f;
    const float C2     = -2.12194440e-4f;
    const float p0     = 1.9875691500e-4f;
    const float p1     = 1.3981999507e-3f;
    const float p2     = 8.3334519073e-3f;
    const float p3     = 4.1665795894e-2f;
    const float p4     = 1.6666665459e-1f;
    const float p5     = 5.0000001201e-1f;
    x = fminf(x, exp_hi);
    x = fmaxf(x, exp_lo);
    float fx = floorf(fmaf(x, LOG2EF, 0.5f));
    float tmp = __fmul_rn(C1, fx);
    float z   = __fmul_rn(C2, fx);
    float r   = __fsub_rn(x, tmp);
    r = __fsub_rn(r, z);
    float r2 = __fmul_rn(r, r);
    float y = p0;
    y = fmaf(y, r, p1); y = fmaf(y, r, p2); y = fmaf(y, r, p3);
    y = fmaf(y, r, p4); y = fmaf(y, r, p5);
    y = fmaf(y, r2, r);
    y = __fadd_rn(y, 1.0f);
    int n = (int)fx;
    float pow2n = __int_as_float((n + 127) << 23);
    return __fmul_rn(y, pow2n);
}

__device__ __forceinline__ void amx(float& bv, int& bi, float v2, int i2) {
    if (v2 > bv || (v2 == bv && i2 < bi)) { bv = v2; bi = i2; }
}
__device__ __forceinline__ unsigned f2tf32(float f) {
    unsigned u;
    asm("cvt.rna.tf32.f32 %0, %1;" : "=r"(u) : "f"(f));
    return u;
}

// ---------------- kernel 1a: per-row norms, XLA:CPU sharded-vector reduce replica ----
__global__ void row_norms(const float* __restrict__ in, float* __restrict__ den, int rows) {
    int r = blockIdx.x * blockDim.x + threadIdx.x;
    if (r >= rows) return;
    const float* v = in + (size_t)r * DD;
    float s[16];
    #pragma unroll
    for (int l = 0; l < 16; l++) s[l] = 0.f;
    for (int t = 0; t < DD; t += 16) {
        #pragma unroll
        for (int l = 0; l < 16; l++) {
            float x = v[t + l];
            s[l] = __fadd_rn(s[l], __fmul_rn(x, x));
        }
    }
    float V[4];
    #pragma unroll
    for (int l = 0; l < 4; l++)
        V[l] = __fadd_rn(__fadd_rn(s[l], s[4 + l]), __fadd_rn(s[8 + l], s[12 + l]));
    float total = __fadd_rn(__fadd_rn(V[0], V[2]), __fadd_rn(V[1], V[3]));
    den[r] = fmaxf(sqrtf(total), 1e-8f);
}

// ---------------- kernel 1b: elementwise divide ----------------
__global__ void div_rows(const float* __restrict__ in, const float* __restrict__ den,
                         float* __restrict__ out) {
    int row = blockIdx.x;
    float d = den[row];
    out[(size_t)row * DD + threadIdx.x] = __fdiv_rn(in[(size_t)row * DD + threadIdx.x], d);
}

// ---------------- kernel 2: tf32 mma.sync batched NT-GEMM, xla-exp epilogue -----------
// (R9 kernel verbatim: passed correctness with w rel_err 1.8e-5; inferred ~170 us)
#define TBM 128
#define TBN 128
#define TBK 32
#define KPAD 36
__global__ __launch_bounds__(256)
void gemm_tf32_exp(const float* __restrict__ A, const float* __restrict__ Bm,
                   float* __restrict__ C) {
    __shared__ unsigned As[TBM][KPAD];
    __shared__ unsigned Bs[TBN][KPAD];

    const int b  = blockIdx.z;
    const int bm = blockIdx.y * TBM;
    const int bn = blockIdx.x * TBN;
    const float* Ab = A  + (size_t)b * MM * DD;
    const float* Bb = Bm + (size_t)b * NN * DD;
    float*       Cb = C  + (size_t)b * MM * NN;

    const int tid  = threadIdx.x;
    const int warp = tid >> 5;
    const int lane = tid & 31;
    const int wm   = (warp & 1) * 64;
    const int wn   = (warp >> 1) * 32;
    const int gid  = lane >> 2;
    const int thr  = lane & 3;

    const int lrow = tid >> 1;
    const int lk   = (tid & 1) * 16;

    float acc[4][4][4];
    #pragma unroll
    for (int i = 0; i < 4; i++)
        #pragma unroll
        for (int j = 0; j < 4; j++)
            #pragma unroll
            for (int c = 0; c < 4; c++) acc[i][j][c] = 0.f;

    float4 ra[4], rb[4];
    const float* aptr = Ab + (size_t)(bm + lrow) * DD + lk;
    const float* bptr = Bb + (size_t)(bn + lrow) * DD + lk;
    #pragma unroll
    for (int i = 0; i < 4; i++) {
        ra[i] = *(const float4*)(aptr + i * 4);
        rb[i] = *(const float4*)(bptr + i * 4);
    }

    for (int it = 0; it < DD / TBK; it++) {
        #pragma unroll
        for (int i = 0; i < 4; i++) {
            uint4 ua, ub;
            ua.x = f2tf32(ra[i].x); ua.y = f2tf32(ra[i].y);
            ua.z = f2tf32(ra[i].z); ua.w = f2tf32(ra[i].w);
            ub.x = f2tf32(rb[i].x); ub.y = f2tf32(rb[i].y);
            ub.z = f2tf32(rb[i].z); ub.w = f2tf32(rb[i].w);
            *(uint4*)&As[lrow][lk + i * 4] = ua;
            *(uint4*)&Bs[lrow][lk + i * 4] = ub;
        }
        __syncthreads();

        if (it + 1 < DD / TBK) {
            const float* ap = aptr + (it + 1) * TBK;
            const float* bp = bptr + (it + 1) * TBK;
            #pragma unroll
            for (int i = 0; i < 4; i++) {
                ra[i] = *(const float4*)(ap + i * 4);
                rb[i] = *(const float4*)(bp + i * 4);
            }
        }

        #pragma unroll
        for (int ks = 0; ks < 4; ks++) {
            const int kb = ks * 8;
            unsigned a0[4], a1[4], a2[4], a3[4], b0[4], b1[4];
            #pragma unroll
            for (int mf = 0; mf < 4; mf++) {
                const int r0 = wm + mf * 16 + gid;
                a0[mf] = As[r0][kb + thr];
                a1[mf] = As[r0 + 8][kb + thr];
                a2[mf] = As[r0][kb + thr + 4];
                a3[mf] = As[r0 + 8][kb + thr + 4];
            }
            #pragma unroll
            for (int nf = 0; nf < 4; nf++) {
                const int c0 = wn + nf * 8 + gid;
                b0[nf] = Bs[c0][kb + thr];
                b1[nf] = Bs[c0][kb + thr + 4];
            }
            #pragma unroll
            for (int mf = 0; mf < 4; mf++)
                #pragma unroll
                for (int nf = 0; nf < 4; nf++) {
                    asm volatile(
                        "mma.sync.aligned.m16n8k8.row.col.f32.tf32.tf32.f32 "
                        "{%0,%1,%2,%3}, {%4,%5,%6,%7}, {%8,%9}, {%0,%1,%2,%3};"
                        : "+f"(acc[mf][nf][0]), "+f"(acc[mf][nf][1]),
                          "+f"(acc[mf][nf][2]), "+f"(acc[mf][nf][3])
                        : "r"(a0[mf]), "r"(a1[mf]), "r"(a2[mf]), "r"(a3[mf]),
                          "r"(b0[nf]), "r"(b1[nf]));
                }
        }
        __syncthreads();
    }

    #pragma unroll
    for (int mf = 0; mf < 4; mf++) {
        const int row = bm + wm + mf * 16 + gid;
        #pragma unroll
        for (int nf = 0; nf < 4; nf++) {
            const int col = bn + wn + nf * 8 + thr * 2;
            float2 v0, v1;
            v0.x = xla_expf(acc[mf][nf][0]);
            v0.y = xla_expf(acc[mf][nf][1]);
            v1.x = xla_expf(acc[mf][nf][2]);
            v1.y = xla_expf(acc[mf][nf][3]);
            *(float2*)&Cb[(size_t)row * NN + col]       = v0;
            *(float2*)&Cb[(size_t)(row + 8) * NN + col] = v1;
        }
    }
}

// ---------------- kernel 3: row kernel (approx top-16 + threshold extras + fast exact
// ---------------- re-rank; exact w2 path identical to R8) -----------------------------
__global__ __launch_bounds__(256)
void row_topk(const float* __restrict__ w_in, const float* __restrict__ f1,
              const float* __restrict__ f1n, const float* __restrict__ f2n,
              const float* __restrict__ p, const float* __restrict__ q,
              float* __restrict__ f_out, float* __restrict__ idx_out,
              float* __restrict__ w_out) {
    const int m = blockIdx.x;
    const int b = blockIdx.y;
    const int tid  = threadIdx.x;   // 256
    const int lane = tid & 31;
    const int wid  = tid >> 5;

    __shared__ __align__(16) float ws[NN];
    __shared__ __align__(16) float w2s[8 * 257 + 8];  // 2064 >= 2048; reused as stage
    __shared__ float f2row[DD];
    __shared__ float sv[8];
    __shared__ int   si[8];
    __shared__ int   b4i[KCOOR];
    __shared__ float b4v[KCOOR];
    __shared__ int   cand[NCMAX];
    __shared__ float keyf[NCMAX];
    __shared__ int   sel[KSIM];
    __shared__ int   s_cnt;
    __shared__ float s_thresh;

    const size_t rowbase = ((size_t)b * MM + m) * NN;

    for (int n = tid; n < NN; n += 256) ws[n] = w_in[rowbase + n];
    if (tid < DD) f2row[tid] = f2n[((size_t)b * MM + m) * DD + tid];

    // exact w2 row (frozen bit recipe)
    const float qx = q[((size_t)b * MM + m) * 3 + 0];
    const float qy = q[((size_t)b * MM + m) * 3 + 1];
    const float qz = q[((size_t)b * MM + m) * 3 + 2];
    const float qq = __fadd_rn(__fadd_rn(__fmul_rn(qx, qx), __fmul_rn(qy, qy)),
                               __fmul_rn(qz, qz));
    for (int n = tid; n < NN; n += 256) {
        const float px = p[((size_t)b * NN + n) * 3 + 0];
        const float py = p[((size_t)b * NN + n) * 3 + 1];
        const float pz = p[((size_t)b * NN + n) * 3 + 2];
        const float pp = __fadd_rn(__fadd_rn(__fmul_rn(px, px), __fmul_rn(py, py)),
                                   __fmul_rn(pz, pz));
        const float dot3 = fmaf(qz, pz, fmaf(qy, py, __fmul_rn(qx, px)));
        const float d2 = __fsub_rn(__fadd_rn(qq, pp), __fmul_rn(2.0f, dot3));
        w2s[n] = xla_expf(-d2);
    }
    __syncthreads();

    // exact top-4 of w2 (tie -> smaller index); record boosts, add into approx ws
    for (int t = 0; t < KCOOR; t++) {
        float bv = -CUDART_INF_F; int bi = 1 << 30;
        for (int n4 = tid; n4 < NN / 4; n4 += 256) {
            float4 v = *(const float4*)&w2s[n4 * 4];
            amx(bv, bi, v.x, n4 * 4 + 0);
            amx(bv, bi, v.y, n4 * 4 + 1);
            amx(bv, bi, v.z, n4 * 4 + 2);
            amx(bv, bi, v.w, n4 * 4 + 3);
        }
        #pragma unroll
        for (int o = 16; o > 0; o >>= 1) {
            float v2 = __shfl_xor_sync(0xffffffffu, bv, o);
            int   i2 = __shfl_xor_sync(0xffffffffu, bi, o);
            amx(bv, bi, v2, i2);
        }
        if (lane == 0) { sv[wid] = bv; si[wid] = bi; }
        __syncthreads();
        if (tid == 0) {
            float fv = sv[0]; int fi = si[0];
            #pragma unroll
            for (int i = 1; i < 8; i++) amx(fv, fi, sv[i], si[i]);
            b4i[t] = fi; b4v[t] = fv;
            ws[fi] = __fadd_rn(ws[fi], fv);
            w2s[fi] = -CUDART_INF_F;
        }
        __syncthreads();
    }

    if (w_out) {
        for (int n = tid; n < NN; n += 256) w_out[rowbase + n] = ws[n];
        __syncthreads();
    }

    // approx top-16 (destructive); capture threshold after the 16th
    for (int t = 0; t < KSIM; t++) {
        float bv = -CUDART_INF_F; int bi = 1 << 30;
        for (int n4 = tid; n4 < NN / 4; n4 += 256) {
            float4 v = *(const float4*)&ws[n4 * 4];
            amx(bv, bi, v.x, n4 * 4 + 0);
            amx(bv, bi, v.y, n4 * 4 + 1);
            amx(bv, bi, v.z, n4 * 4 + 2);
            amx(bv, bi, v.w, n4 * 4 + 3);
        }
        #pragma unroll
        for (int o = 16; o > 0; o >>= 1) {
            float v2 = __shfl_xor_sync(0xffffffffu, bv, o);
            int   i2 = __shfl_xor_sync(0xffffffffu, bi, o);
            amx(bv, bi, v2, i2);
        }
        if (lane == 0) { sv[wid] = bv; si[wid] = bi; }
        __syncthreads();
        if (tid == 0) {
            float fv = sv[0]; int fi = si[0];
            #pragma unroll
            for (int i = 1; i < 8; i++) amx(fv, fi, sv[i], si[i]);
            cand[t] = fi;
            ws[fi] = -CUDART_INF_F;
            if (t == KSIM - 1) { s_thresh = fv - EPSW; s_cnt = KSIM; }
        }
        __syncthreads();
    }

    // threshold sweep: collect extras within EPSW of the approx cutoff
    {
        const float th = s_thresh;
        for (int n = tid; n < NN; n += 256) {
            if (ws[n] > th) {
                int pos = atomicAdd(&s_cnt, 1);
                if (pos < NCMAX) cand[pos] = n;
            }
        }
    }
    __syncthreads();
    const int nc = (s_cnt < NCMAX) ? s_cnt : NCMAX;

    // exact keys: stage candidate rows coalesced into smem (reusing w2s), then
    // sequential fmaf chains (frozen bit recipe) + accurate exp, 8 per group
    for (int g = 0; g * 8 < nc; g++) {
        __syncthreads();   // previous group's chains done before overwriting stage
        const int r  = tid >> 5;        // 0..7 candidate-in-group
        const int c0 = (tid & 31) * 8;  // 8 floats per lane
        if (g * 8 + r < nc) {
            const float* src = f1n + ((size_t)b * NN + cand[g * 8 + r]) * DD + c0;
            float4 v0 = *(const float4*)(src);
            float4 v1 = *(const float4*)(src + 4);
            float* dst = &w2s[r * 257 + c0];
            dst[0] = v0.x; dst[1] = v0.y; dst[2] = v0.z; dst[3] = v0.w;
            dst[4] = v1.x; dst[5] = v1.y; dst[6] = v1.z; dst[7] = v1.w;
        }
        __syncthreads();
        if (tid < 8 && g * 8 + tid < nc) {
            const float* fr = &w2s[tid * 257];
            float acc = 0.f;
            for (int k = 0; k < DD; k++)
                acc = fmaf(f2row[k], fr[k], acc);
            keyf[g * 8 + tid] = xla_expf(acc);
        }
    }
    __syncthreads();

    // exact boosts
    if (tid == 0) {
        #pragma unroll
        for (int t = 0; t < KCOOR; t++) {
            for (int c = 0; c < nc; c++) {
                if (cand[c] == b4i[t]) {
                    keyf[c] = __fadd_rn(keyf[c], b4v[t]);
                    break;
                }
            }
        }
    }
    __syncthreads();

    // exact top-16 over nc keys: 16 warp-shuffle argmax rounds (tie -> smaller n)
    if (wid == 0) {
        float myk = (lane < nc) ? keyf[lane] : -CUDART_INF_F;
        int   myi = (lane < nc) ? cand[lane] : (1 << 30);
        for (int t = 0; t < KSIM; t++) {
            float bv = myk; int bi = myi; int bl = lane;
            #pragma unroll
            for (int o = 16; o > 0; o >>= 1) {
                float v2 = __shfl_xor_sync(0xffffffffu, bv, o);
                int   i2 = __shfl_xor_sync(0xffffffffu, bi, o);
                int   l2 = __shfl_xor_sync(0xffffffffu, bl, o);
                if (v2 > bv || (v2 == bv && i2 < bi)) { bv = v2; bi = i2; bl = l2; }
            }
            if (lane == 0) sel[t] = bi;
            if (lane == bl) myk = -CUDART_INF_F;
        }
    }
    __syncthreads();

    if (idx_out && tid < KSIM)
        idx_out[((size_t)b * MM + m) * KSIM + tid] = (float)sel[tid];

    if (f_out) {
        const int d = tid;
        float s = 0.f, mx = -CUDART_INF_F;
        #pragma unroll
        for (int k = 0; k < KSIM; k++) {
            float v = f1[((size_t)b * NN + sel[k]) * DD + d];
            s += v;
            mx = fmaxf(mx, v);
        }
        size_t fo = ((size_t)b * MM + m) * (2 * DD);
        f_out[fo + d]      = s * (1.0f / 16.0f);
        f_out[fo + DD + d] = mx;
    }
}

// ---------------- launch ----------------
extern "C" void kernel_launch(void* const* d_in, const int* in_sizes, int n_in,
                              void* d_out, int out_size) {
    const float* f1 = (const float*)d_in[0];
    const float* f2 = (const float*)d_in[1];
    const float* p  = (const float*)d_in[2];
    const float* q  = (const float*)d_in[3];

    float* f1n;  cudaGetSymbolAddress((void**)&f1n,  g_f1n);
    float* f2n;  cudaGetSymbolAddress((void**)&f2n,  g_f2n);
    float* wbuf; cudaGetSymbolAddress((void**)&wbuf, g_w);
    float* den1; cudaGetSymbolAddress((void**)&den1, g_den1);
    float* den2; cudaGetSymbolAddress((void**)&den2, g_den2);

    const size_t F_E = (size_t)BB * MM * (2 * DD);
    const size_t I_E = (size_t)BB * MM * KSIM;
    const size_t W_E = (size_t)BB * MM * NN;

    float* out = (float*)d_out;
    float* f_out = nullptr; float* idx_out = nullptr; float* w_out = nullptr;
    size_t osz = (size_t)out_size;
    if (osz >= F_E + I_E + W_E) {
        f_out = out; idx_out = out + F_E; w_out = out + F_E + I_E;
    } else if (osz == F_E + I_E) {
        f_out = out; idx_out = out + F_E;
    } else if (osz == W_E) {
        w_out = out;
    } else {
        f_out = out;
    }

    row_norms<<<(BB * NN + 255) / 256, 256>>>(f1, den1, BB * NN);
    row_norms<<<(BB * MM + 255) / 256, 256>>>(f2, den2, BB * MM);
    div_rows<<<BB * NN, 256>>>(f1, den1, f1n);
    div_rows<<<BB * MM, 256>>>(f2, den2, f2n);

    dim3 ggrid(NN / TBN, MM / TBM, BB);
    gemm_tf32_exp<<<ggrid, 256>>>(f2n, f1n, wbuf);

    dim3 rgrid(MM, BB);
    row_topk<<<rgrid, 256>>>(wbuf, f1, f1n, f2n, p, q, f_out, idx_out, w_out);
}

// round 16
// speedup vs baseline: 1.8354x; 1.8354x over previous
#include <cuda_runtime.h>
#include <math_constants.h>
#include <cstdint>

// Problem constants (fixed by setup_inputs)
#define BB 8
#define NN 2048
#define MM 2048
#define DD 256
#define KSIM 16
#define KCOOR 4

// ---------------- device scratch (allocation-free) ----------------
__device__ float g_f1n[(size_t)BB * NN * DD];
__device__ float g_f2n[(size_t)BB * MM * DD];
__device__ float g_w[(size_t)BB * MM * NN];   // xla-exp(w1), bit-exact

// ---------------- accurate-class expf replica (frozen bit recipe) ----------------
__device__ __forceinline__ float xla_expf(float x) {
    const float exp_hi = 88.3762626647950f;
    const float exp_lo = -88.3762626647949f;
    const float LOG2EF = 1.44269504088896341f;
    const float C1     = 0.693359375f;
    const float C2     = -2.12194440e-4f;
    const float p0     = 1.9875691500e-4f;
    const float p1     = 1.3981999507e-3f;
    const float p2     = 8.3334519073e-3f;
    const float p3     = 4.1665795894e-2f;
    const float p4     = 1.6666665459e-1f;
    const float p5     = 5.0000001201e-1f;
    x = fminf(x, exp_hi);
    x = fmaxf(x, exp_lo);
    float fx = floorf(fmaf(x, LOG2EF, 0.5f));
    float tmp = __fmul_rn(C1, fx);
    float z   = __fmul_rn(C2, fx);
    float r   = __fsub_rn(x, tmp);
    r = __fsub_rn(r, z);
    float r2 = __fmul_rn(r, r);
    float y = p0;
    y = fmaf(y, r, p1); y = fmaf(y, r, p2); y = fmaf(y, r, p3);
    y = fmaf(y, r, p4); y = fmaf(y, r, p5);
    y = fmaf(y, r2, r);
    y = __fadd_rn(y, 1.0f);
    int n = (int)fx;
    float pow2n = __int_as_float((n + 127) << 23);
    return __fmul_rn(y, pow2n);
}

// ---------------- argmax helper (desc value, tie -> smaller index) ----------------
__device__ __forceinline__ void amx(float& bv, int& bi, float v2, int i2) {
    if (v2 > bv || (v2 == bv && i2 < bi)) { bv = v2; bi = i2; }
}

// ---------------- kernel 1: fused norms + divide (one warp per row) ----------------
// Exact replica of the XLA sharded reduce: s[l] += v[16t+l]^2 (t ascending, separate
// mul/add rounds), V[l] = (s[l]+s[4+l])+(s[8+l]+s[12+l]), total = (V0+V2)+(V1+V3),
// den = max(sqrt(total), 1e-8), out = v / den (div.rn).
__global__ __launch_bounds__(256)
void norm_div(const float* __restrict__ in, float* __restrict__ out) {
    const int wid  = threadIdx.x >> 5;
    const int lane = threadIdx.x & 31;
    const int row  = blockIdx.x * 8 + wid;

    __shared__ float buf[8][DD];

    const float4* src = (const float4*)(in + (size_t)row * DD);
    float4 a = src[lane];
    float4 b = src[lane + 32];
    *(float4*)&buf[wid][lane * 4]       = a;
    *(float4*)&buf[wid][128 + lane * 4] = b;
    __syncwarp();

    // lanes 0..15: shard l accumulates buf[16t + l]^2, t ascending
    float s = 0.f;
    if (lane < 16) {
        #pragma unroll
        for (int t = 0; t < 16; t++) {
            float x = buf[wid][t * 16 + lane];
            s = __fadd_rn(s, __fmul_rn(x, x));
        }
    }
    // V[l] = (s[l] + s[l+4]) + (s[l+8] + s[l+12]) on lanes 0..3
    float s4  = __shfl_sync(0xffffffffu, s, lane + 4);
    float s8  = __shfl_sync(0xffffffffu, s, lane + 8);
    float s12 = __shfl_sync(0xffffffffu, s, lane + 12);
    float V = __fadd_rn(__fadd_rn(s, s4), __fadd_rn(s8, s12));
    // total = (V0 + V2) + (V1 + V3) on lane 0
    float V1 = __shfl_sync(0xffffffffu, V, 1);
    float V2 = __shfl_sync(0xffffffffu, V, 2);
    float V3 = __shfl_sync(0xffffffffu, V, 3);
    float total = __fadd_rn(__fadd_rn(V, V2), __fadd_rn(V1, V3));
    float den = fmaxf(sqrtf(total), 1e-8f);
    den = __shfl_sync(0xffffffffu, den, 0);

    float4* dst = (float4*)(out + (size_t)row * DD);
    float4 oa, ob;
    oa.x = __fdiv_rn(a.x, den); oa.y = __fdiv_rn(a.y, den);
    oa.z = __fdiv_rn(a.z, den); oa.w = __fdiv_rn(a.w, den);
    ob.x = __fdiv_rn(b.x, den); ob.y = __fdiv_rn(b.y, den);
    ob.z = __fdiv_rn(b.z, den); ob.w = __fdiv_rn(b.w, den);
    dst[lane]      = oa;
    dst[lane + 32] = ob;
}

// ---------------- kernel 2: batched NT-SGEMM, sequential-k FFMA chain, xla-exp --------
#define GBM 128
#define GBN 128
#define GBK 8
#define GTM 8
#define GTN 8
__global__ __launch_bounds__(256, 2)
void gemm_exp(const float* __restrict__ A, const float* __restrict__ Bm,
              float* __restrict__ C) {
    const int b  = blockIdx.z;
    const int bm = blockIdx.y * GBM;
    const int bn = blockIdx.x * GBN;
    const float* Ab = A  + (size_t)b * MM * DD;
    const float* Bb = Bm + (size_t)b * NN * DD;
    float*       Cb = C  + (size_t)b * MM * NN;

    __shared__ float As[GBK][GBM];
    __shared__ float Bs[GBK][GBN];

    const int tid = threadIdx.x;
    const int ty  = tid / 16;
    const int tx  = tid % 16;
    const int lrow = tid >> 1;
    const int lk4  = (tid & 1) * 4;

    float acc[GTM][GTN];
    #pragma unroll
    for (int i = 0; i < GTM; i++)
        #pragma unroll
        for (int j = 0; j < GTN; j++) acc[i][j] = 0.f;

    for (int k0 = 0; k0 < DD; k0 += GBK) {
        float4 a4 = *(const float4*)(Ab + (size_t)(bm + lrow) * DD + k0 + lk4);
        float4 b4 = *(const float4*)(Bb + (size_t)(bn + lrow) * DD + k0 + lk4);
        __syncthreads();
        As[lk4 + 0][lrow] = a4.x; As[lk4 + 1][lrow] = a4.y;
        As[lk4 + 2][lrow] = a4.z; As[lk4 + 3][lrow] = a4.w;
        Bs[lk4 + 0][lrow] = b4.x; Bs[lk4 + 1][lrow] = b4.y;
        Bs[lk4 + 2][lrow] = b4.z; Bs[lk4 + 3][lrow] = b4.w;
        __syncthreads();
        #pragma unroll
        for (int k = 0; k < GBK; k++) {
            float ar[GTM], br[GTN];
            #pragma unroll
            for (int i = 0; i < GTM; i += 4) {
                float4 t = *(const float4*)&As[k][ty * GTM + i];
                ar[i] = t.x; ar[i+1] = t.y; ar[i+2] = t.z; ar[i+3] = t.w;
            }
            #pragma unroll
            for (int j = 0; j < GTN; j += 4) {
                float4 t = *(const float4*)&Bs[k][tx * GTN + j];
                br[j] = t.x; br[j+1] = t.y; br[j+2] = t.z; br[j+3] = t.w;
            }
            #pragma unroll
            for (int i = 0; i < GTM; i++)
                #pragma unroll
                for (int j = 0; j < GTN; j++)
                    acc[i][j] = fmaf(ar[i], br[j], acc[i][j]);
        }
    }

    #pragma unroll
    for (int i = 0; i < GTM; i++) {
        size_t rowoff = (size_t)(bm + ty * GTM + i) * NN + bn + tx * GTN;
        #pragma unroll
        for (int j = 0; j < GTN; j += 4) {
            float4 o;
            o.x = xla_expf(acc[i][j + 0]);
            o.y = xla_expf(acc[i][j + 1]);
            o.z = xla_expf(acc[i][j + 2]);
            o.w = xla_expf(acc[i][j + 3]);
            *(float4*)(Cb + rowoff + j) = o;
        }
    }
}

// ---------------- kernel 3: row kernel with tournament argmax (bit-exact) -------------
// 8 slices of 256; per round: tid0 argmax over 8 slice maxima, dirty-slice rescan by
// owning warp. Exactly equivalent to global (desc value, asc index) argmax.
__global__ __launch_bounds__(256)
void row_topk(const float* __restrict__ w_in, const float* __restrict__ f1,
              const float* __restrict__ p, const float* __restrict__ q,
              float* __restrict__ f_out, float* __restrict__ idx_out,
              float* __restrict__ w_out) {
    const int m = blockIdx.x;
    const int b = blockIdx.y;
    const int tid  = threadIdx.x;   // 256
    const int lane = tid & 31;
    const int wid  = tid >> 5;

    __shared__ __align__(16) float ws[NN];
    __shared__ __align__(16) float w2s[NN];
    __shared__ float sv[8];
    __shared__ int   si[8];
    __shared__ int   sel[KSIM];
    __shared__ int   s_dirty;

    const size_t rowbase = ((size_t)b * MM + m) * NN;

    for (int n = tid; n < NN; n += 256) ws[n] = w_in[rowbase + n];

    const float qx = q[((size_t)b * MM + m) * 3 + 0];
    const float qy = q[((size_t)b * MM + m) * 3 + 1];
    const float qz = q[((size_t)b * MM + m) * 3 + 2];
    const float qq = __fadd_rn(__fadd_rn(__fmul_rn(qx, qx), __fmul_rn(qy, qy)),
                               __fmul_rn(qz, qz));
    for (int n = tid; n < NN; n += 256) {
        const float px = p[((size_t)b * NN + n) * 3 + 0];
        const float py = p[((size_t)b * NN + n) * 3 + 1];
        const float pz = p[((size_t)b * NN + n) * 3 + 2];
        const float pp = __fadd_rn(__fadd_rn(__fmul_rn(px, px), __fmul_rn(py, py)),
                                   __fmul_rn(pz, pz));
        const float dot3 = fmaf(qz, pz, fmaf(qy, py, __fmul_rn(qx, px)));
        const float d2 = __fsub_rn(__fadd_rn(qq, pp), __fmul_rn(2.0f, dot3));
        w2s[n] = xla_expf(-d2);
    }
    __syncthreads();

    // init slice maxima for w2s: warp w scans [256w, 256w+256)
    {
        float bv = -CUDART_INF_F; int bi = 1 << 30;
        const int base = wid * 256;
        #pragma unroll
        for (int i = 0; i < 8; i++)
            amx(bv, bi, w2s[base + i * 32 + lane], base + i * 32 + lane);
        #pragma unroll
        for (int o = 16; o > 0; o >>= 1) {
            float v2 = __shfl_xor_sync(0xffffffffu, bv, o);
            int   i2 = __shfl_xor_sync(0xffffffffu, bi, o);
            amx(bv, bi, v2, i2);
        }
        if (lane == 0) { sv[wid] = bv; si[wid] = bi; }
    }
    __syncthreads();

    // top-4 of w2: tournament rounds with boost into ws
    for (int t = 0; t < KCOOR; t++) {
        if (tid == 0) {
            float fv = sv[0]; int fi = si[0];
            #pragma unroll
            for (int i = 1; i < 8; i++) amx(fv, fi, sv[i], si[i]);
            ws[fi] = __fadd_rn(ws[fi], fv);
            w2s[fi] = -CUDART_INF_F;
            s_dirty = fi >> 8;
        }
        __syncthreads();
        if (wid == s_dirty) {
            float bv = -CUDART_INF_F; int bi = 1 << 30;
            const int base = wid * 256;
            #pragma unroll
            for (int i = 0; i < 8; i++)
                amx(bv, bi, w2s[base + i * 32 + lane], base + i * 32 + lane);
            #pragma unroll
            for (int o = 16; o > 0; o >>= 1) {
                float v2 = __shfl_xor_sync(0xffffffffu, bv, o);
                int   i2 = __shfl_xor_sync(0xffffffffu, bi, o);
                amx(bv, bi, v2, i2);
            }
            if (lane == 0) { sv[wid] = bv; si[wid] = bi; }
        }
        __syncthreads();
    }

    if (w_out) {
        for (int n = tid; n < NN; n += 256) w_out[rowbase + n] = ws[n];
        __syncthreads();
    }

    // init slice maxima for ws
    {
        float bv = -CUDART_INF_F; int bi = 1 << 30;
        const int base = wid * 256;
        #pragma unroll
        for (int i = 0; i < 8; i++)
            amx(bv, bi, ws[base + i * 32 + lane], base + i * 32 + lane);
        #pragma unroll
        for (int o = 16; o > 0; o >>= 1) {
            float v2 = __shfl_xor_sync(0xffffffffu, bv, o);
            int   i2 = __shfl_xor_sync(0xffffffffu, bi, o);
            amx(bv, bi, v2, i2);
        }
        if (lane == 0) { sv[wid] = bv; si[wid] = bi; }
    }
    __syncthreads();

    // top-16 of ws: tournament rounds
    for (int t = 0; t < KSIM; t++) {
        if (tid == 0) {
            float fv = sv[0]; int fi = si[0];
            #pragma unroll
            for (int i = 1; i < 8; i++) amx(fv, fi, sv[i], si[i]);
            sel[t] = fi;
            ws[fi] = -CUDART_INF_F;
            s_dirty = fi >> 8;
        }
        __syncthreads();
        if (wid == s_dirty) {
            float bv = -CUDART_INF_F; int bi = 1 << 30;
            const int base = wid * 256;
            #pragma unroll
            for (int i = 0; i < 8; i++)
                amx(bv, bi, ws[base + i * 32 + lane], base + i * 32 + lane);
            #pragma unroll
            for (int o = 16; o > 0; o >>= 1) {
                float v2 = __shfl_xor_sync(0xffffffffu, bv, o);
                int   i2 = __shfl_xor_sync(0xffffffffu, bi, o);
                amx(bv, bi, v2, i2);
            }
            if (lane == 0) { sv[wid] = bv; si[wid] = bi; }
        }
        __syncthreads();
    }

    if (idx_out && tid < KSIM)
        idx_out[((size_t)b * MM + m) * KSIM + tid] = (float)sel[tid];

    if (f_out) {
        const int d = tid;   // DD == 256 == blockDim
        float s = 0.f, mx = -CUDART_INF_F;
        #pragma unroll
        for (int k = 0; k < KSIM; k++) {
            float v = f1[((size_t)b * NN + sel[k]) * DD + d];
            s += v;
            mx = fmaxf(mx, v);
        }
        size_t fo = ((size_t)b * MM + m) * (2 * DD);
        f_out[fo + d]      = s * (1.0f / 16.0f);
        f_out[fo + DD + d] = mx;
    }
}

// ---------------- launch ----------------
extern "C" void kernel_launch(void* const* d_in, const int* in_sizes, int n_in,
                              void* d_out, int out_size) {
    const float* f1 = (const float*)d_in[0];
    const float* f2 = (const float*)d_in[1];
    const float* p  = (const float*)d_in[2];
    const float* q  = (const float*)d_in[3];

    float* f1n;  cudaGetSymbolAddress((void**)&f1n,  g_f1n);
    float* f2n;  cudaGetSymbolAddress((void**)&f2n,  g_f2n);
    float* wbuf; cudaGetSymbolAddress((void**)&wbuf, g_w);

    const size_t F_E = (size_t)BB * MM * (2 * DD);
    const size_t I_E = (size_t)BB * MM * KSIM;
    const size_t W_E = (size_t)BB * MM * NN;

    float* out = (float*)d_out;
    float* f_out = nullptr; float* idx_out = nullptr; float* w_out = nullptr;
    size_t osz = (size_t)out_size;
    if (osz >= F_E + I_E + W_E) {
        f_out = out; idx_out = out + F_E; w_out = out + F_E + I_E;
    } else if (osz == F_E + I_E) {
        f_out = out; idx_out = out + F_E;
    } else if (osz == W_E) {
        w_out = out;
    } else {
        f_out = out;
    }

    norm_div<<<BB * NN / 8, 256>>>(f1, f1n);
    norm_div<<<BB * MM / 8, 256>>>(f2, f2n);

    dim3 ggrid(NN / GBN, MM / GBM, BB);
    gemm_exp<<<ggrid, 256>>>(f2n, f1n, wbuf);

    dim3 rgrid(MM, BB);
    row_topk<<<rgrid, 256>>>(wbuf, f1, p, q, f_out, idx_out, w_out);
}

// round 17
// speedup vs baseline: 1.8513x; 1.0087x over previous
#include <cuda_runtime.h>
#include <math_constants.h>
#include <cstdint>

// Problem constants (fixed by setup_inputs)
#define BB 8
#define NN 2048
#define MM 2048
#define DD 256
#define KSIM 16
#define KCOOR 4

// ---------------- device scratch (allocation-free) ----------------
__device__ float g_f1n[(size_t)BB * NN * DD];
__device__ float g_f2n[(size_t)BB * MM * DD];
__device__ float g_w[(size_t)BB * MM * NN];   // used only if harness doesn't want w

// ---------------- accurate-class expf replica (frozen bit recipe) ----------------
__device__ __forceinline__ float xla_expf(float x) {
    const float exp_hi = 88.3762626647950f;
    const float exp_lo = -88.3762626647949f;
    const float LOG2EF = 1.44269504088896341f;
    const float C1     = 0.693359375f;
    const float C2     = -2.12194440e-4f;
    const float p0     = 1.9875691500e-4f;
    const float p1     = 1.3981999507e-3f;
    const float p2     = 8.3334519073e-3f;
    const float p3     = 4.1665795894e-2f;
    const float p4     = 1.6666665459e-1f;
    const float p5     = 5.0000001201e-1f;
    x = fminf(x, exp_hi);
    x = fmaxf(x, exp_lo);
    float fx = floorf(fmaf(x, LOG2EF, 0.5f));
    float tmp = __fmul_rn(C1, fx);
    float z   = __fmul_rn(C2, fx);
    float r   = __fsub_rn(x, tmp);
    r = __fsub_rn(r, z);
    float r2 = __fmul_rn(r, r);
    float y = p0;
    y = fmaf(y, r, p1); y = fmaf(y, r, p2); y = fmaf(y, r, p3);
    y = fmaf(y, r, p4); y = fmaf(y, r, p5);
    y = fmaf(y, r2, r);
    y = __fadd_rn(y, 1.0f);
    int n = (int)fx;
    float pow2n = __int_as_float((n + 127) << 23);
    return __fmul_rn(y, pow2n);
}

// ---------------- argmax helper (desc value, tie -> smaller index) ----------------
__device__ __forceinline__ void amx(float& bv, int& bi, float v2, int i2) {
    if (v2 > bv || (v2 == bv && i2 < bi)) { bv = v2; bi = i2; }
}

// ---------------- kernel 1: fused norms + divide (one warp per row) ----------------
__global__ __launch_bounds__(256)
void norm_div(const float* __restrict__ in, float* __restrict__ out) {
    const int wid  = threadIdx.x >> 5;
    const int lane = threadIdx.x & 31;
    const int row  = blockIdx.x * 8 + wid;

    __shared__ float buf[8][DD];

    const float4* src = (const float4*)(in + (size_t)row * DD);
    float4 a = src[lane];
    float4 b = src[lane + 32];
    *(float4*)&buf[wid][lane * 4]       = a;
    *(float4*)&buf[wid][128 + lane * 4] = b;
    __syncwarp();

    // lanes 0..15: shard l accumulates buf[16t + l]^2, t ascending (XLA replica)
    float s = 0.f;
    if (lane < 16) {
        #pragma unroll
        for (int t = 0; t < 16; t++) {
            float x = buf[wid][t * 16 + lane];
            s = __fadd_rn(s, __fmul_rn(x, x));
        }
    }
    float s4  = __shfl_sync(0xffffffffu, s, lane + 4);
    float s8  = __shfl_sync(0xffffffffu, s, lane + 8);
    float s12 = __shfl_sync(0xffffffffu, s, lane + 12);
    float V = __fadd_rn(__fadd_rn(s, s4), __fadd_rn(s8, s12));
    float V1 = __shfl_sync(0xffffffffu, V, 1);
    float V2 = __shfl_sync(0xffffffffu, V, 2);
    float V3 = __shfl_sync(0xffffffffu, V, 3);
    float total = __fadd_rn(__fadd_rn(V, V2), __fadd_rn(V1, V3));
    float den = fmaxf(sqrtf(total), 1e-8f);
    den = __shfl_sync(0xffffffffu, den, 0);

    float4* dst = (float4*)(out + (size_t)row * DD);
    float4 oa, ob;
    oa.x = __fdiv_rn(a.x, den); oa.y = __fdiv_rn(a.y, den);
    oa.z = __fdiv_rn(a.z, den); oa.w = __fdiv_rn(a.w, den);
    ob.x = __fdiv_rn(b.x, den); ob.y = __fdiv_rn(b.y, den);
    ob.z = __fdiv_rn(b.z, den); ob.w = __fdiv_rn(b.w, den);
    dst[lane]      = oa;
    dst[lane + 32] = ob;
}

// ---------------- kernel 2: batched NT-SGEMM, sequential-k FFMA chain, xla-exp --------
#define GBM 128
#define GBN 128
#define GBK 8
#define GTM 8
#define GTN 8
__global__ __launch_bounds__(256, 2)
void gemm_exp(const float* __restrict__ A, const float* __restrict__ Bm,
              float* __restrict__ C) {
    const int b  = blockIdx.z;
    const int bm = blockIdx.y * GBM;
    const int bn = blockIdx.x * GBN;
    const float* Ab = A  + (size_t)b * MM * DD;
    const float* Bb = Bm + (size_t)b * NN * DD;
    float*       Cb = C  + (size_t)b * MM * NN;

    __shared__ float As[GBK][GBM];
    __shared__ float Bs[GBK][GBN];

    const int tid = threadIdx.x;
    const int ty  = tid / 16;
    const int tx  = tid % 16;
    const int lrow = tid >> 1;
    const int lk4  = (tid & 1) * 4;

    float acc[GTM][GTN];
    #pragma unroll
    for (int i = 0; i < GTM; i++)
        #pragma unroll
        for (int j = 0; j < GTN; j++) acc[i][j] = 0.f;

    for (int k0 = 0; k0 < DD; k0 += GBK) {
        float4 a4 = *(const float4*)(Ab + (size_t)(bm + lrow) * DD + k0 + lk4);
        float4 b4 = *(const float4*)(Bb + (size_t)(bn + lrow) * DD + k0 + lk4);
        __syncthreads();
        As[lk4 + 0][lrow] = a4.x; As[lk4 + 1][lrow] = a4.y;
        As[lk4 + 2][lrow] = a4.z; As[lk4 + 3][lrow] = a4.w;
        Bs[lk4 + 0][lrow] = b4.x; Bs[lk4 + 1][lrow] = b4.y;
        Bs[lk4 + 2][lrow] = b4.z; Bs[lk4 + 3][lrow] = b4.w;
        __syncthreads();
        #pragma unroll
        for (int k = 0; k < GBK; k++) {
            float ar[GTM], br[GTN];
            #pragma unroll
            for (int i = 0; i < GTM; i += 4) {
                float4 t = *(const float4*)&As[k][ty * GTM + i];
                ar[i] = t.x; ar[i+1] = t.y; ar[i+2] = t.z; ar[i+3] = t.w;
            }
            #pragma unroll
            for (int j = 0; j < GTN; j += 4) {
                float4 t = *(const float4*)&Bs[k][tx * GTN + j];
                br[j] = t.x; br[j+1] = t.y; br[j+2] = t.z; br[j+3] = t.w;
            }
            #pragma unroll
            for (int i = 0; i < GTM; i++)
                #pragma unroll
                for (int j = 0; j < GTN; j++)
                    acc[i][j] = fmaf(ar[i], br[j], acc[i][j]);
        }
    }

    #pragma unroll
    for (int i = 0; i < GTM; i++) {
        size_t rowoff = (size_t)(bm + ty * GTM + i) * NN + bn + tx * GTN;
        #pragma unroll
        for (int j = 0; j < GTN; j += 4) {
            float4 o;
            o.x = xla_expf(acc[i][j + 0]);
            o.y = xla_expf(acc[i][j + 1]);
            o.z = xla_expf(acc[i][j + 2]);
            o.w = xla_expf(acc[i][j + 3]);
            *(float4*)(Cb + rowoff + j) = o;
        }
    }
}

// ---------------- kernel 3: row kernel, tournament argmax; w boosted in place ---------
// wrow: GEMM already wrote exp(w1) here (this IS the w output region when requested).
// Only the 4 boosted entries are written back (w_store != 0).
__global__ __launch_bounds__(256)
void row_topk(float* __restrict__ wrow, const float* __restrict__ f1,
              const float* __restrict__ p, const float* __restrict__ q,
              float* __restrict__ f_out, float* __restrict__ idx_out,
              int w_store) {
    const int m = blockIdx.x;
    const int b = blockIdx.y;
    const int tid  = threadIdx.x;   // 256
    const int lane = tid & 31;
    const int wid  = tid >> 5;

    __shared__ __align__(16) float ws[NN];
    __shared__ __align__(16) float w2s[NN];
    __shared__ float sv[8];
    __shared__ int   si[8];
    __shared__ int   sel[KSIM];
    __shared__ int   s_dirty;

    const size_t rowbase = ((size_t)b * MM + m) * NN;

    for (int n = tid; n < NN; n += 256) ws[n] = wrow[rowbase + n];

    const float qx = q[((size_t)b * MM + m) * 3 + 0];
    const float qy = q[((size_t)b * MM + m) * 3 + 1];
    const float qz = q[((size_t)b * MM + m) * 3 + 2];
    const float qq = __fadd_rn(__fadd_rn(__fmul_rn(qx, qx), __fmul_rn(qy, qy)),
                               __fmul_rn(qz, qz));
    for (int n = tid; n < NN; n += 256) {
        const float px = p[((size_t)b * NN + n) * 3 + 0];
        const float py = p[((size_t)b * NN + n) * 3 + 1];
        const float pz = p[((size_t)b * NN + n) * 3 + 2];
        const float pp = __fadd_rn(__fadd_rn(__fmul_rn(px, px), __fmul_rn(py, py)),
                                   __fmul_rn(pz, pz));
        const float dot3 = fmaf(qz, pz, fmaf(qy, py, __fmul_rn(qx, px)));
        const float d2 = __fsub_rn(__fadd_rn(qq, pp), __fmul_rn(2.0f, dot3));
        w2s[n] = xla_expf(-d2);
    }
    __syncthreads();

    // init slice maxima for w2s: warp w owns [256w, 256w+256)
    {
        float bv = -CUDART_INF_F; int bi = 1 << 30;
        const int base = wid * 256;
        #pragma unroll
        for (int i = 0; i < 8; i++)
            amx(bv, bi, w2s[base + i * 32 + lane], base + i * 32 + lane);
        #pragma unroll
        for (int o = 16; o > 0; o >>= 1) {
            float v2 = __shfl_xor_sync(0xffffffffu, bv, o);
            int   i2 = __shfl_xor_sync(0xffffffffu, bi, o);
            amx(bv, bi, v2, i2);
        }
        if (lane == 0) { sv[wid] = bv; si[wid] = bi; }
    }
    __syncthreads();

    // top-4 of w2: tournament; boost ws in smem + write back ONLY boosted entries
    for (int t = 0; t < KCOOR; t++) {
        if (tid == 0) {
            float fv = sv[0]; int fi = si[0];
            #pragma unroll
            for (int i = 1; i < 8; i++) amx(fv, fi, sv[i], si[i]);
            float nb = __fadd_rn(ws[fi], fv);
            ws[fi] = nb;
            if (w_store) wrow[rowbase + fi] = nb;
            w2s[fi] = -CUDART_INF_F;
            s_dirty = fi >> 8;
        }
        __syncthreads();
        if (wid == s_dirty) {
            float bv = -CUDART_INF_F; int bi = 1 << 30;
            const int base = wid * 256;
            #pragma unroll
            for (int i = 0; i < 8; i++)
                amx(bv, bi, w2s[base + i * 32 + lane], base + i * 32 + lane);
            #pragma unroll
            for (int o = 16; o > 0; o >>= 1) {
                float v2 = __shfl_xor_sync(0xffffffffu, bv, o);
                int   i2 = __shfl_xor_sync(0xffffffffu, bi, o);
                amx(bv, bi, v2, i2);
            }
            if (lane == 0) { sv[wid] = bv; si[wid] = bi; }
        }
        __syncthreads();
    }

    // init slice maxima for ws
    {
        float bv = -CUDART_INF_F; int bi = 1 << 30;
        const int base = wid * 256;
        #pragma unroll
        for (int i = 0; i < 8; i++)
            amx(bv, bi, ws[base + i * 32 + lane], base + i * 32 + lane);
        #pragma unroll
        for (int o = 16; o > 0; o >>= 1) {
            float v2 = __shfl_xor_sync(0xffffffffu, bv, o);
            int   i2 = __shfl_xor_sync(0xffffffffu, bi, o);
            amx(bv, bi, v2, i2);
        }
        if (lane == 0) { sv[wid] = bv; si[wid] = bi; }
    }
    __syncthreads();

    // top-16 of ws: tournament rounds
    for (int t = 0; t < KSIM; t++) {
        if (tid == 0) {
            float fv = sv[0]; int fi = si[0];
            #pragma unroll
            for (int i = 1; i < 8; i++) amx(fv, fi, sv[i], si[i]);
            sel[t] = fi;
            ws[fi] = -CUDART_INF_F;
            s_dirty = fi >> 8;
        }
        __syncthreads();
        if (wid == s_dirty) {
            float bv = -CUDART_INF_F; int bi = 1 << 30;
            const int base = wid * 256;
            #pragma unroll
            for (int i = 0; i < 8; i++)
                amx(bv, bi, ws[base + i * 32 + lane], base + i * 32 + lane);
            #pragma unroll
            for (int o = 16; o > 0; o >>= 1) {
                float v2 = __shfl_xor_sync(0xffffffffu, bv, o);
                int   i2 = __shfl_xor_sync(0xffffffffu, bi, o);
                amx(bv, bi, v2, i2);
            }
            if (lane == 0) { sv[wid] = bv; si[wid] = bi; }
        }
        __syncthreads();
    }

    if (idx_out && tid < KSIM)
        idx_out[((size_t)b * MM + m) * KSIM + tid] = (float)sel[tid];

    if (f_out) {
        const int d = tid;   // DD == 256 == blockDim
        float s = 0.f, mx = -CUDART_INF_F;
        #pragma unroll
        for (int k = 0; k < KSIM; k++) {
            float v = f1[((size_t)b * NN + sel[k]) * DD + d];
            s += v;
            mx = fmaxf(mx, v);
        }
        size_t fo = ((size_t)b * MM + m) * (2 * DD);
        f_out[fo + d]      = s * (1.0f / 16.0f);
        f_out[fo + DD + d] = mx;
    }
}

// ---------------- launch ----------------
extern "C" void kernel_launch(void* const* d_in, const int* in_sizes, int n_in,
                              void* d_out, int out_size) {
    const float* f1 = (const float*)d_in[0];
    const float* f2 = (const float*)d_in[1];
    const float* p  = (const float*)d_in[2];
    const float* q  = (const float*)d_in[3];

    float* f1n;  cudaGetSymbolAddress((void**)&f1n,  g_f1n);
    float* f2n;  cudaGetSymbolAddress((void**)&f2n,  g_f2n);
    float* wbuf; cudaGetSymbolAddress((void**)&wbuf, g_w);

    const size_t F_E = (size_t)BB * MM * (2 * DD);
    const size_t I_E = (size_t)BB * MM * KSIM;
    const size_t W_E = (size_t)BB * MM * NN;

    float* out = (float*)d_out;
    float* f_out = nullptr; float* idx_out = nullptr; float* w_out = nullptr;
    size_t osz = (size_t)out_size;
    if (osz >= F_E + I_E + W_E) {
        f_out = out; idx_out = out + F_E; w_out = out + F_E + I_E;
    } else if (osz == F_E + I_E) {
        f_out = out; idx_out = out + F_E;
    } else if (osz == W_E) {
        w_out = out;
    } else {
        f_out = out;
    }

    // GEMM writes w directly into the output region when w is requested
    float* wtarget = w_out ? w_out : wbuf;

    norm_div<<<BB * NN / 8, 256>>>(f1, f1n);
    norm_div<<<BB * MM / 8, 256>>>(f2, f2n);

    dim3 ggrid(NN / GBN, MM / GBM, BB);
    gemm_exp<<<ggrid, 256>>>(f2n, f1n, wtarget);

    dim3 rgrid(MM, BB);
    row_topk<<<rgrid, 256>>>(wtarget, f1, p, q, f_out, idx_out, w_out ? 1 : 0);
}